// round 5
// baseline (speedup 1.0000x reference)
#include <cuda_runtime.h>
#include <cuda_bf16.h>

#define NUM_CLASSES 10

// One WARP per batch, 32-bit indexing, no shared memory, no barriers.
// Lanes 0..23 each own (channel, row) of the 3x8x8 top-left patch and load
// the 8-float row as two float4 (LDG.128 x2, row starts 16B-aligned).
// Butterfly shuffles give every lane the total; lanes 0..9 write the logits
// as one coalesced 40B burst.
__global__ __launch_bounds__(32, 16)
void ldc_kernel(const float* __restrict__ x, float* __restrict__ out) {
    const unsigned b    = blockIdx.x;      // batch 0..63
    const unsigned lane = threadIdx.x;     // 0..31

    float v = 0.0f;
    if (lane < 24u) {
        const unsigned c = lane >> 3;      // channel 0..2
        const unsigned r = lane & 7u;      // row 0..7
        // 32-bit offset: max = 64*3*512*512 = 50,331,648 < 2^31
        // ((b*3 + c) << 18) + (r << 9)   [512*512 = 2^18, 512 = 2^9]
        const unsigned idx = ((b * 3u + c) << 18) + (r << 9);
        const float4* p = (const float4*)(x + idx);
        float4 a0 = p[0];
        float4 a1 = p[1];
        v = ((a0.x + a0.y) + (a0.z + a0.w)) + ((a1.x + a1.y) + (a1.z + a1.w));
    }

    // Butterfly reduce: all lanes end with the full sum over 192 elements.
    #pragma unroll
    for (int off = 16; off > 0; off >>= 1)
        v += __shfl_xor_sync(0xFFFFFFFFu, v, off);

    const float mean = v / 192.0f;
    // Python int() truncates toward zero; % with positive modulus is non-negative.
    int t = (int)truncf(mean * 10.0f);
    int pred = t % NUM_CLASSES;
    if (pred < 0) pred += NUM_CLASSES;

    if (lane < NUM_CLASSES)
        out[b * NUM_CLASSES + lane] = ((int)lane == pred) ? 10.0f : 0.0f;
}

extern "C" void kernel_launch(void* const* d_in, const int* in_sizes, int n_in,
                              void* d_out, int out_size) {
    const float* x = (const float*)d_in[0];
    float* out = (float*)d_out;
    ldc_kernel<<<64, 32>>>(x, out);
}

// round 6
// speedup vs baseline: 1.0385x; 1.0385x over previous
#include <cuda_runtime.h>
#include <cuda_bf16.h>

#define NUM_CLASSES 10

// One CTA per batch, 192 threads = 3 channels * 8 rows * 8 cols (the R4
// configuration, which measured 4.608us). Each thread loads one float of
// the top-left 8x8 patch with 32-bit indexing, warp-reduces, leaders store
// partials to smem. Single barrier; then lanes 0..9 of warp 0 each re-sum
// the 6 partials (broadcast LDS), compute pred identically, and write one
// logit each (coalesced 40B burst). Second barrier of R4 eliminated.
__global__ __launch_bounds__(192, 8)
void ldc_kernel(const float* __restrict__ x, float* __restrict__ out) {
    const unsigned b   = blockIdx.x;      // batch 0..63
    const unsigned tid = threadIdx.x;     // 0..191

    // tid -> (c, r, col)
    const unsigned c   = tid >> 6;
    const unsigned w   = tid & 63u;
    const unsigned r   = w >> 3;
    const unsigned col = w & 7u;

    // 32-bit offset: max = 64*3*512*512 = 50,331,648 < 2^31
    const unsigned idx = ((b * 3u + c) << 18) + (r << 9) + col;
    float v = x[idx];

    #pragma unroll
    for (int off = 16; off > 0; off >>= 1)
        v += __shfl_down_sync(0xFFFFFFFFu, v, off);

    __shared__ float partial[6];
    const unsigned warp = tid >> 5;
    if ((tid & 31u) == 0) partial[warp] = v;
    __syncthreads();

    // Lanes 0..9 (warp 0) each redundantly compute the total and pred —
    // identical fp operations in identical order, so identical results.
    if (tid < NUM_CLASSES) {
        float total = partial[0] + partial[1] + partial[2]
                    + partial[3] + partial[4] + partial[5];
        float mean = total / 192.0f;
        // Python int() truncates toward zero; % with positive modulus is
        // non-negative.
        int t = (int)truncf(mean * 10.0f);
        int pred = t % NUM_CLASSES;
        if (pred < 0) pred += NUM_CLASSES;

        out[b * NUM_CLASSES + tid] = ((int)tid == pred) ? 10.0f : 0.0f;
    }
}

extern "C" void kernel_launch(void* const* d_in, const int* in_sizes, int n_in,
                              void* d_out, int out_size) {
    const float* x = (const float*)d_in[0];
    float* out = (float*)d_out;
    ldc_kernel<<<64, 192>>>(x, out);
}

// round 7
// speedup vs baseline: 1.5000x; 1.4444x over previous
#include <cuda_runtime.h>
#include <cuda_bf16.h>

#define NUM_CLASSES 10

// EXACT resubmission of the Round-4 kernel (measured 4.608us) to test
// reproducibility of that draw, per rigor.md re-bench discipline.
// One CTA per batch, 192 threads = 3 channels * 8 rows * 8 cols.
// Each thread loads one float of the top-left 8x8 patch (32-bit indexing),
// warp-reduces, block-combines via smem, and threads 0..9 write the logits
// as one coalesced burst.
__global__ __launch_bounds__(192, 8)
void ldc_kernel(const float* __restrict__ x, float* __restrict__ out) {
    const unsigned b   = blockIdx.x;      // batch 0..63
    const unsigned tid = threadIdx.x;     // 0..191

    // tid -> (c, r, col)
    const unsigned c   = tid >> 6;
    const unsigned w   = tid & 63u;
    const unsigned r   = w >> 3;
    const unsigned col = w & 7u;

    // 32-bit offset: max = 64*3*512*512 = 50,331,648 < 2^31
    const unsigned idx = ((b * 3u + c) << 18) + (r << 9) + col;  // 512*512 = 2^18, 512 = 2^9
    float v = x[idx];

    #pragma unroll
    for (int off = 16; off > 0; off >>= 1)
        v += __shfl_down_sync(0xFFFFFFFFu, v, off);

    __shared__ float partial[6];
    __shared__ int s_pred;
    const unsigned warp = tid >> 5;
    if ((tid & 31u) == 0) partial[warp] = v;
    __syncthreads();

    if (tid == 0) {
        float total = partial[0] + partial[1] + partial[2]
                    + partial[3] + partial[4] + partial[5];
        float mean = total / 192.0f;
        // Python int() truncates toward zero; % with positive modulus is non-negative.
        int t = (int)truncf(mean * 10.0f);
        int pred = t % NUM_CLASSES;
        if (pred < 0) pred += NUM_CLASSES;
        s_pred = pred;
    }
    __syncthreads();

    if (tid < NUM_CLASSES)
        out[b * NUM_CLASSES + tid] = ((int)tid == s_pred) ? 10.0f : 0.0f;
}

extern "C" void kernel_launch(void* const* d_in, const int* in_sizes, int n_in,
                              void* d_out, int out_size) {
    const float* x = (const float*)d_in[0];
    float* out = (float*)d_out;
    ldc_kernel<<<64, 192>>>(x, out);
}